// round 2
// baseline (speedup 1.0000x reference)
#include <cuda_runtime.h>
#include <math.h>

// ---------------------------------------------------------------------------
// Problem constants
// ---------------------------------------------------------------------------
#define B       16384
#define HID     512
#define NDETER  512
#define NGATE   1536          // 3 * NDETER
#define KIN     1084          // 1024 stoch + 60 actions
#define KOBS    5632          // 512 deter + 5120 obs_enc
#define NSTATS  1024          // 32 * 32
#define OUTW    2560          // 512 + 1024 + 1024
#define LNEPS   1e-3f
#define UNIMIX  0.01f

// ---------------------------------------------------------------------------
// Scratch (device globals; no runtime allocation allowed)
// ---------------------------------------------------------------------------
__device__ float g_xbuf[(size_t)B * HID];     //  33.5 MB
__device__ float g_gi  [(size_t)B * NGATE];   // 100.7 MB
__device__ float g_gh  [(size_t)B * NGATE];   // 100.7 MB
__device__ float g_ybuf[(size_t)B * HID];     //  33.5 MB

// ---------------------------------------------------------------------------
// Generic tiled fp32 GEMM:  C[M,N] = A[M,K] * W[N,K]^T (+ bias)
// A is a 2-segment row-major matrix: cols [0,K1) from A1 (stride lda1),
// cols [K1,K) from A2 (stride lda2). All segment boundaries / K are
// multiples of 4 so float4 loads never straddle.
// Tile: 128x128x16, 256 threads, 8x8 per thread.
// ---------------------------------------------------------------------------
#define BM 128
#define BN 128
#define BK 16
#define TM 8
#define TN 8
#define SPAD 4

__global__ __launch_bounds__(256)
void gemm_seg_kernel(const float* __restrict__ A1, int lda1, int K1,
                     const float* __restrict__ A2, int lda2,
                     const float* __restrict__ W,
                     const float* __restrict__ bias,
                     float* __restrict__ C, int ldc,
                     int M, int N, int K)
{
    __shared__ float As[BK][BM + SPAD];
    __shared__ float Ws[BK][BN + SPAD];

    const int tid = threadIdx.x;
    const int tx  = tid & 15;          // n direction (16)
    const int ty  = tid >> 4;          // m direction (16)
    const int mBase = blockIdx.y * BM;
    const int nBase = blockIdx.x * BN;

    float acc[TM][TN];
#pragma unroll
    for (int i = 0; i < TM; i++)
#pragma unroll
        for (int j = 0; j < TN; j++) acc[i][j] = 0.f;

    for (int k0 = 0; k0 < K; k0 += BK) {
        // ---- global -> registers (2 float4 each for A and W) ----
        float4 aReg[2], wReg[2];
#pragma unroll
        for (int it = 0; it < 2; it++) {
            int idx = tid + it * 256;
            int row = idx >> 2;                 // 0..127
            int kq  = (idx & 3) << 2;           // 0,4,8,12
            int k   = k0 + kq;
            float4 av = make_float4(0.f, 0.f, 0.f, 0.f);
            float4 wv = make_float4(0.f, 0.f, 0.f, 0.f);
            if (k < K) {
                if (k < K1)
                    av = *(const float4*)(A1 + (size_t)(mBase + row) * lda1 + k);
                else
                    av = *(const float4*)(A2 + (size_t)(mBase + row) * lda2 + (k - K1));
                wv = *(const float4*)(W + (size_t)(nBase + row) * K + k);
            }
            aReg[it] = av;
            wReg[it] = wv;
        }
        __syncthreads();   // previous tile's compute must be done
        // ---- registers -> shared (transposed to [k][m/n]) ----
#pragma unroll
        for (int it = 0; it < 2; it++) {
            int idx = tid + it * 256;
            int row = idx >> 2;
            int kq  = (idx & 3) << 2;
            As[kq + 0][row] = aReg[it].x;
            As[kq + 1][row] = aReg[it].y;
            As[kq + 2][row] = aReg[it].z;
            As[kq + 3][row] = aReg[it].w;
            Ws[kq + 0][row] = wReg[it].x;
            Ws[kq + 1][row] = wReg[it].y;
            Ws[kq + 2][row] = wReg[it].z;
            Ws[kq + 3][row] = wReg[it].w;
        }
        __syncthreads();
        // ---- compute ----
#pragma unroll
        for (int kk = 0; kk < BK; kk++) {
            float4 a0 = *(const float4*)&As[kk][ty * TM];
            float4 a1 = *(const float4*)&As[kk][ty * TM + 4];
            float4 w0 = *(const float4*)&Ws[kk][tx * TN];
            float4 w1 = *(const float4*)&Ws[kk][tx * TN + 4];
            float a[TM] = {a0.x, a0.y, a0.z, a0.w, a1.x, a1.y, a1.z, a1.w};
            float w[TN] = {w0.x, w0.y, w0.z, w0.w, w1.x, w1.y, w1.z, w1.w};
#pragma unroll
            for (int i = 0; i < TM; i++)
#pragma unroll
                for (int j = 0; j < TN; j++)
                    acc[i][j] = fmaf(a[i], w[j], acc[i][j]);
        }
    }

    // ---- epilogue: + bias, store float4 ----
    float4 bv0 = make_float4(0.f, 0.f, 0.f, 0.f);
    float4 bv1 = make_float4(0.f, 0.f, 0.f, 0.f);
    if (bias) {
        bv0 = *(const float4*)(bias + nBase + tx * TN);
        bv1 = *(const float4*)(bias + nBase + tx * TN + 4);
    }
#pragma unroll
    for (int i = 0; i < TM; i++) {
        float* cp = C + (size_t)(mBase + ty * TM + i) * ldc + nBase + tx * TN;
        float4 o0 = make_float4(acc[i][0] + bv0.x, acc[i][1] + bv0.y,
                                acc[i][2] + bv0.z, acc[i][3] + bv0.w);
        float4 o1 = make_float4(acc[i][4] + bv1.x, acc[i][5] + bv1.y,
                                acc[i][6] + bv1.z, acc[i][7] + bv1.w);
        *(float4*)cp       = o0;
        *(float4*)(cp + 4) = o1;
    }
}

// ---------------------------------------------------------------------------
// LayerNorm(eps=1e-3) + SiLU over rows of 512. 128 threads/row, 4 elems each.
// ---------------------------------------------------------------------------
__device__ __forceinline__ float block_reduce_128(float v, float* sm)
{
#pragma unroll
    for (int o = 16; o > 0; o >>= 1) v += __shfl_xor_sync(0xffffffffu, v, o);
    int w = threadIdx.x >> 5;
    if ((threadIdx.x & 31) == 0) sm[w] = v;
    __syncthreads();
    float r = sm[0] + sm[1] + sm[2] + sm[3];
    __syncthreads();
    return r;
}

__global__ void ln_silu_kernel(const float* __restrict__ in, float* __restrict__ out,
                               const float* __restrict__ g, const float* __restrict__ bb)
{
    __shared__ float sm[4];
    const int row = blockIdx.x;
    const float4 v  = ((const float4*)(in + (size_t)row * HID))[threadIdx.x];
    float s = v.x + v.y + v.z + v.w;
    float mean = block_reduce_128(s, sm) * (1.f / HID);
    float dx = v.x - mean, dy = v.y - mean, dz = v.z - mean, dw = v.w - mean;
    float q = dx * dx + dy * dy + dz * dz + dw * dw;
    float var = block_reduce_128(q, sm) * (1.f / HID);
    float rs = rsqrtf(var + LNEPS);
    float4 gg = ((const float4*)g)[threadIdx.x];
    float4 bv = ((const float4*)bb)[threadIdx.x];
    float t0 = dx * rs * gg.x + bv.x;
    float t1 = dy * rs * gg.y + bv.y;
    float t2 = dz * rs * gg.z + bv.z;
    float t3 = dw * rs * gg.w + bv.w;
    float4 o;
    o.x = t0 / (1.f + expf(-t0));
    o.y = t1 / (1.f + expf(-t1));
    o.z = t2 / (1.f + expf(-t2));
    o.w = t3 / (1.f + expf(-t3));
    ((float4*)(out + (size_t)row * HID))[threadIdx.x] = o;
}

// ---------------------------------------------------------------------------
// GRU gates (torch order r,z,n) -> deter written into d_out cols [0,512)
// ---------------------------------------------------------------------------
__device__ __forceinline__ float sigmoidf_(float x) { return 1.f / (1.f + expf(-x)); }

__global__ void gru_kernel(const float* __restrict__ gi, const float* __restrict__ gh,
                           const float* __restrict__ deter_old, float* __restrict__ out)
{
    int idx = blockIdx.x * blockDim.x + threadIdx.x;
    int b = idx >> 9;
    int h = idx & 511;
    size_t base = (size_t)b * NGATE;
    float r = sigmoidf_(gi[base + h]        + gh[base + h]);
    float z = sigmoidf_(gi[base + 512 + h]  + gh[base + 512 + h]);
    float n = tanhf    (gi[base + 1024 + h] + r * gh[base + 1024 + h]);
    float d = (1.f - z) * n + z * deter_old[(size_t)b * NDETER + h];
    out[(size_t)b * OUTW + h] = d;
}

// ---------------------------------------------------------------------------
// Per-group-32 softmax -> unimix probs -> argmax one-hot.
// One warp per (row, group). Reads logits from d_out cols [512,1536),
// writes one-hot to cols [1536,2560).  stoch == onehot in forward value.
// ---------------------------------------------------------------------------
__global__ void softmax_onehot_kernel(float* __restrict__ out)
{
    int gw   = (blockIdx.x * blockDim.x + threadIdx.x) >> 5;
    int lane = threadIdx.x & 31;
    int b    = gw >> 5;
    int grp  = gw & 31;
    float* row = out + (size_t)b * OUTW;
    float l = row[512 + grp * 32 + lane];
    float m = l;
#pragma unroll
    for (int o = 16; o > 0; o >>= 1) m = fmaxf(m, __shfl_xor_sync(0xffffffffu, m, o));
    float e = expf(l - m);
    float s = e;
#pragma unroll
    for (int o = 16; o > 0; o >>= 1) s += __shfl_xor_sync(0xffffffffu, s, o);
    float p = (1.f - UNIMIX) * (e / s) + UNIMIX / 32.f;
    // argmax with first-index tie break (matches jnp.argmax)
    float bp = p; int bi = lane;
#pragma unroll
    for (int o = 16; o > 0; o >>= 1) {
        float op = __shfl_xor_sync(0xffffffffu, bp, o);
        int   oi = __shfl_xor_sync(0xffffffffu, bi, o);
        if (op > bp || (op == bp && oi < bi)) { bp = op; bi = oi; }
    }
    row[1536 + grp * 32 + lane] = (lane == bi) ? 1.f : 0.f;
}

// ---------------------------------------------------------------------------
// Launch
// ---------------------------------------------------------------------------
extern "C" void kernel_launch(void* const* d_in, const int* in_sizes, int n_in,
                              void* d_out_, int out_size)
{
    const float* obs   = (const float*)d_in[0];   // (B, 5120)
    const float* act   = (const float*)d_in[1];   // (B, 60)
    const float* stoch = (const float*)d_in[2];   // (B, 1024)
    const float* deter = (const float*)d_in[3];   // (B, 512)
    const float* W_in  = (const float*)d_in[4];   // (512, 1084)
    const float* gin   = (const float*)d_in[5];
    const float* bin   = (const float*)d_in[6];
    const float* W_ih  = (const float*)d_in[7];   // (1536, 512)
    const float* W_hh  = (const float*)d_in[8];   // (1536, 512)
    const float* b_ih  = (const float*)d_in[9];
    const float* b_hh  = (const float*)d_in[10];
    const float* W_obs = (const float*)d_in[11];  // (512, 5632)
    const float* gobs  = (const float*)d_in[12];
    const float* bobs  = (const float*)d_in[13];
    const float* W_st  = (const float*)d_in[14];  // (1024, 512)
    const float* b_st  = (const float*)d_in[15];
    float* out = (float*)d_out_;

    float *xbuf, *gi, *gh, *ybuf;
    cudaGetSymbolAddress((void**)&xbuf, g_xbuf);
    cudaGetSymbolAddress((void**)&gi,   g_gi);
    cudaGetSymbolAddress((void**)&gh,   g_gh);
    cudaGetSymbolAddress((void**)&ybuf, g_ybuf);

    dim3 blk(256);
    const int MT = B / BM;   // 128 m-tiles

    // 1) x_pre = [stoch | actions] @ W_in^T            (M=B, N=512, K=1084)
    gemm_seg_kernel<<<dim3(HID / BN, MT), blk>>>(
        stoch, 1024, 1024, act, 60, W_in, nullptr, xbuf, HID, B, HID, KIN);
    // 2) x = silu(LN(x_pre))
    ln_silu_kernel<<<B, 128>>>(xbuf, xbuf, gin, bin);
    // 3) gi = x @ W_ih^T + b_ih                        (N=1536, K=512)
    gemm_seg_kernel<<<dim3(NGATE / BN, MT), blk>>>(
        xbuf, HID, HID, nullptr, 0, W_ih, b_ih, gi, NGATE, B, NGATE, HID);
    // 4) gh = deter @ W_hh^T + b_hh
    gemm_seg_kernel<<<dim3(NGATE / BN, MT), blk>>>(
        deter, NDETER, NDETER, nullptr, 0, W_hh, b_hh, gh, NGATE, B, NGATE, NDETER);
    // 5) GRU -> deter_new in d_out[:, 0:512]
    gru_kernel<<<(B * NDETER) / 256, 256>>>(gi, gh, deter, out);
    // 6) y_pre = [deter_new | obs_enc] @ W_obs^T       (N=512, K=5632)
    gemm_seg_kernel<<<dim3(HID / BN, MT), blk>>>(
        out, OUTW, NDETER, obs, 5120, W_obs, nullptr, ybuf, HID, B, HID, KOBS);
    // 7) y = silu(LN(y_pre))
    ln_silu_kernel<<<B, 128>>>(ybuf, ybuf, gobs, bobs);
    // 8) logits = y @ W_stats^T + b_stats -> d_out[:, 512:1536]
    gemm_seg_kernel<<<dim3(NSTATS / BN, MT), blk>>>(
        ybuf, HID, HID, nullptr, 0, W_st, b_st, out + 512, OUTW, B, NSTATS, HID);
    // 9) softmax/unimix/argmax one-hot -> d_out[:, 1536:2560]
    softmax_onehot_kernel<<<(B * 32 * 32) / 256, 256>>>(out);
}

// round 5
// speedup vs baseline: 1.9650x; 1.9650x over previous
#include <cuda_runtime.h>
#include <cuda_fp16.h>
#include <math.h>

// ---------------------------------------------------------------------------
// Problem constants
// ---------------------------------------------------------------------------
#define B       16384
#define HID     512
#define NDETER  512
#define NGATE   1536
#define KIN     1084
#define KOBS    5632
#define NSTATS  1024
#define OUTW    2560
#define LNEPS   1e-3f
#define UNIMIX  0.01f
#define LO_SCALE    2048.0f
#define LO_UNSCALE  (1.0f / 2048.0f)

// ---------------------------------------------------------------------------
// Scratch (device globals; no runtime allocation allowed)
// ---------------------------------------------------------------------------
__device__ float g_xbuf[(size_t)B * HID];
__device__ float g_gi  [(size_t)B * NGATE];
__device__ float g_gh  [(size_t)B * NGATE];
__device__ float g_ybuf[(size_t)B * HID];

// ---------------------------------------------------------------------------
// Helpers
// ---------------------------------------------------------------------------
__device__ __forceinline__ unsigned smem_u32(const void* p) {
    unsigned a;
    asm("{ .reg .u64 t; cvta.to.shared.u64 t, %1; cvt.u32.u64 %0, t; }"
        : "=r"(a) : "l"(p));
    return a;
}

#define MMA16816(acc, a, b0v, b1v)                                            \
    asm volatile(                                                             \
        "mma.sync.aligned.m16n8k16.row.col.f32.f16.f16.f32 "                  \
        "{%0,%1,%2,%3}, {%4,%5,%6,%7}, {%8,%9}, {%0,%1,%2,%3};"               \
        : "+f"((acc)[0]), "+f"((acc)[1]), "+f"((acc)[2]), "+f"((acc)[3])      \
        : "r"((a)[0]), "r"((a)[1]), "r"((a)[2]), "r"((a)[3]),                 \
          "r"(b0v), "r"(b1v))

#define LDMX4(r0, r1, r2, r3, addr)                                           \
    asm volatile("ldmatrix.sync.aligned.m8n8.x4.shared.b16 {%0,%1,%2,%3}, [%4];" \
        : "=r"(r0), "=r"(r1), "=r"(r2), "=r"(r3) : "r"(addr))

// ---------------------------------------------------------------------------
// fp16-split (Ootomo, scaled residual) HMMA GEMM:
//   C[M,N] = A[M,K] * W[N,K]^T (+ bias)
// x = hi + lo/2048 with hi, lo fp16.  acc0 += hi*hi;  acc1 += hi*lo + lo*hi;
// C = acc0 + acc1/2048.  fp32 accumulators -> ~22-bit effective mantissa.
// A is 2-segment: cols [0,K1) from A1 (stride lda1), [K1,K) from A2 (lda2);
// K1 % 32 == 0. CTA tile 128x128, K-chunk 32 fp32, 8 warps (2Mx4N),
// warp tile 64x32, mma m16n8k16.
// smem: 80-byte row pitch (64B data + 16B pad) -> conflict-free ldmatrix.
// ---------------------------------------------------------------------------
#define BKF   32
#define PITCH 80
#define TILE_B  10240               // 128 rows * 80B
#define AH_OFF  0
#define AL_OFF  10240
#define BH_OFF  20480
#define BL_OFF  30720
#define STAGE_B 40960
#define GEMM_SMEM (2 * STAGE_B)

__device__ __forceinline__ void ldg_chunk(float4* v, int k0,
    const float* __restrict__ A1, int lda1, int K1,
    const float* __restrict__ A2, int lda2,
    const float* __restrict__ W, int K, int mBase, int nBase, int tid)
{
    const float* Aseg; int ldA, kOff;
    if (k0 < K1) { Aseg = A1; ldA = lda1; kOff = k0; }
    else         { Aseg = A2; ldA = lda2; kOff = k0 - K1; }
#pragma unroll
    for (int q = 0; q < 8; ++q) {
        const int j   = (q & 3) * 256 + tid;   // 0..1023
        const int row = j >> 3;                // 0..127
        const int c4  = j & 7;                 // float4 index in k
        const int k   = k0 + c4 * 4;
        float4 val = make_float4(0.f, 0.f, 0.f, 0.f);
        if (k < K) {
            if (q < 4)
                val = *(const float4*)(Aseg + (size_t)(mBase + row) * ldA + kOff + c4 * 4);
            else
                val = *(const float4*)(W + (size_t)(nBase + row) * K + k);
        }
        v[q] = val;
    }
}

__device__ __forceinline__ void sts_chunk(const float4* v, unsigned stage, int tid)
{
#pragma unroll
    for (int q = 0; q < 8; ++q) {
        const int j   = (q & 3) * 256 + tid;
        const int row = j >> 3;
        const int c4  = j & 7;
        const unsigned hiA = stage + (q < 4 ? AH_OFF : BH_OFF)
                           + (unsigned)(row * PITCH + c4 * 8);
        const float4 x = v[q];
        __half2 h01 = __floats2half2_rn(x.x, x.y);
        __half2 h23 = __floats2half2_rn(x.z, x.w);
        float2 f01 = __half22float2(h01);
        float2 f23 = __half22float2(h23);
        // residual scaled by 2048 -> fp16 normal range (Ootomo)
        __half2 l01 = __floats2half2_rn((x.x - f01.x) * LO_SCALE,
                                        (x.y - f01.y) * LO_SCALE);
        __half2 l23 = __floats2half2_rn((x.z - f23.x) * LO_SCALE,
                                        (x.w - f23.y) * LO_SCALE);
        unsigned uh0 = *(unsigned*)&h01, uh1 = *(unsigned*)&h23;
        unsigned ul0 = *(unsigned*)&l01, ul1 = *(unsigned*)&l23;
        asm volatile("st.shared.v2.b32 [%0], {%1,%2};"
                     :: "r"(hiA), "r"(uh0), "r"(uh1) : "memory");
        asm volatile("st.shared.v2.b32 [%0], {%1,%2};"
                     :: "r"(hiA + 10240u), "r"(ul0), "r"(ul1) : "memory");
    }
}

__global__ __launch_bounds__(256, 1)
void gemm_hmma(const float* __restrict__ A1, int lda1, int K1,
               const float* __restrict__ A2, int lda2,
               const float* __restrict__ W, const float* __restrict__ bias,
               float* __restrict__ C, int ldc, int K)
{
    extern __shared__ char smem[];
    const unsigned sb = smem_u32(smem);
    const int tid  = threadIdx.x;
    const int lane = tid & 31;
    const int wid  = tid >> 5;
    const int mW   = (wid >> 2) * 64;   // warp M offset in CTA tile
    const int nW   = (wid & 3) * 32;    // warp N offset
    const int mBase = blockIdx.y * 128;
    const int nBase = blockIdx.x * 128;

    float acc0[4][4][4];   // hi*hi
    float acc1[4][4][4];   // hi*lo + lo*hi  (scaled by 2048)
#pragma unroll
    for (int i = 0; i < 4; i++)
#pragma unroll
        for (int j = 0; j < 4; j++)
#pragma unroll
            for (int c = 0; c < 4; c++) { acc0[i][j][c] = 0.f; acc1[i][j][c] = 0.f; }

    const int nch = (K + BKF - 1) / BKF;

    float4 v[8];
    ldg_chunk(v, 0, A1, lda1, K1, A2, lda2, W, K, mBase, nBase, tid);
    sts_chunk(v, sb, tid);
    __syncthreads();

    const unsigned aRow = (unsigned)((mW + (lane & 15)) * PITCH + (lane >> 4) * 16);
    const unsigned bRow = (unsigned)((nW + (lane & 15)) * PITCH + (lane >> 4) * 16);

    for (int it = 0; it < nch; ++it) {
        const unsigned stage = sb + (unsigned)(it & 1) * STAGE_B;
        if (it + 1 < nch)
            ldg_chunk(v, (it + 1) * BKF, A1, lda1, K1, A2, lda2, W, K, mBase, nBase, tid);

#pragma unroll
        for (int kk = 0; kk < 2; ++kk) {
            // --- B fragments for this k16 (4 n-tiles, hi+lo) ---
            unsigned bH[4][2], bL[4][2];
#pragma unroll
            for (int np = 0; np < 2; ++np) {
                unsigned bd = stage + BH_OFF + bRow + (unsigned)(np * 16 * PITCH + kk * 32);
                unsigned r0, r1, r2, r3;
                LDMX4(r0, r1, r2, r3, bd);
                bH[2 * np][0] = r0; bH[2 * np][1] = r2;
                bH[2 * np + 1][0] = r1; bH[2 * np + 1][1] = r3;
                LDMX4(r0, r1, r2, r3, bd + 10240u);
                bL[2 * np][0] = r0; bL[2 * np][1] = r2;
                bL[2 * np + 1][0] = r1; bL[2 * np + 1][1] = r3;
            }
            // --- per m-tile: load A frags, 3 MMAs per n-tile ---
#pragma unroll
            for (int mt = 0; mt < 4; ++mt) {
                unsigned aH[4], aL[4];
                unsigned ad = stage + AH_OFF + aRow + (unsigned)(mt * 16 * PITCH + kk * 32);
                LDMX4(aH[0], aH[1], aH[2], aH[3], ad);
                LDMX4(aL[0], aL[1], aL[2], aL[3], ad + 10240u);
#pragma unroll
                for (int nt = 0; nt < 4; ++nt) {
                    MMA16816(acc0[mt][nt], aH, bH[nt][0], bH[nt][1]);
                    MMA16816(acc1[mt][nt], aH, bL[nt][0], bL[nt][1]);
                    MMA16816(acc1[mt][nt], aL, bH[nt][0], bH[nt][1]);
                }
            }
        }

        if (it + 1 < nch)
            sts_chunk(v, sb + (unsigned)((it + 1) & 1) * STAGE_B, tid);
        __syncthreads();
    }

    // ---- epilogue: C = acc0 + acc1/2048 (+bias) ----
    const int g = lane >> 2, t = lane & 3;
#pragma unroll
    for (int mt = 0; mt < 4; ++mt) {
#pragma unroll
        for (int nt = 0; nt < 4; ++nt) {
            const int row = mBase + mW + mt * 16 + g;
            const int col = nBase + nW + nt * 8 + t * 2;
            float bx = 0.f, by = 0.f;
            if (bias) { bx = bias[col]; by = bias[col + 1]; }
            float2 o0, o1;
            o0.x = fmaf(acc1[mt][nt][0], LO_UNSCALE, acc0[mt][nt][0]) + bx;
            o0.y = fmaf(acc1[mt][nt][1], LO_UNSCALE, acc0[mt][nt][1]) + by;
            o1.x = fmaf(acc1[mt][nt][2], LO_UNSCALE, acc0[mt][nt][2]) + bx;
            o1.y = fmaf(acc1[mt][nt][3], LO_UNSCALE, acc0[mt][nt][3]) + by;
            *(float2*)(C + (size_t)row * ldc + col)       = o0;
            *(float2*)(C + (size_t)(row + 8) * ldc + col) = o1;
        }
    }
}

// ---------------------------------------------------------------------------
// LayerNorm(eps=1e-3) + SiLU (rows of 512; 128 threads/row)
// ---------------------------------------------------------------------------
__device__ __forceinline__ float block_reduce_128(float v, float* sm)
{
#pragma unroll
    for (int o = 16; o > 0; o >>= 1) v += __shfl_xor_sync(0xffffffffu, v, o);
    int w = threadIdx.x >> 5;
    if ((threadIdx.x & 31) == 0) sm[w] = v;
    __syncthreads();
    float r = sm[0] + sm[1] + sm[2] + sm[3];
    __syncthreads();
    return r;
}

__global__ void ln_silu_kernel(const float* __restrict__ in, float* __restrict__ out,
                               const float* __restrict__ g, const float* __restrict__ bb)
{
    __shared__ float sm[4];
    const int row = blockIdx.x;
    const float4 v = ((const float4*)(in + (size_t)row * HID))[threadIdx.x];
    float s = v.x + v.y + v.z + v.w;
    float mean = block_reduce_128(s, sm) * (1.f / HID);
    float dx = v.x - mean, dy = v.y - mean, dz = v.z - mean, dw = v.w - mean;
    float q = dx * dx + dy * dy + dz * dz + dw * dw;
    float var = block_reduce_128(q, sm) * (1.f / HID);
    float rs = rsqrtf(var + LNEPS);
    float4 gg = ((const float4*)g)[threadIdx.x];
    float4 bv = ((const float4*)bb)[threadIdx.x];
    float t0 = dx * rs * gg.x + bv.x;
    float t1 = dy * rs * gg.y + bv.y;
    float t2 = dz * rs * gg.z + bv.z;
    float t3 = dw * rs * gg.w + bv.w;
    float4 o;
    o.x = t0 / (1.f + expf(-t0));
    o.y = t1 / (1.f + expf(-t1));
    o.z = t2 / (1.f + expf(-t2));
    o.w = t3 / (1.f + expf(-t3));
    ((float4*)(out + (size_t)row * HID))[threadIdx.x] = o;
}

// ---------------------------------------------------------------------------
// GRU gates (torch order r,z,n) -> deter into d_out cols [0,512)
// ---------------------------------------------------------------------------
__device__ __forceinline__ float sigmoidf_(float x) { return 1.f / (1.f + expf(-x)); }

__global__ void gru_kernel(const float* __restrict__ gi, const float* __restrict__ gh,
                           const float* __restrict__ deter_old, float* __restrict__ out)
{
    int idx = blockIdx.x * blockDim.x + threadIdx.x;
    int b = idx >> 9;
    int h = idx & 511;
    size_t base = (size_t)b * NGATE;
    float r = sigmoidf_(gi[base + h]        + gh[base + h]);
    float z = sigmoidf_(gi[base + 512 + h]  + gh[base + 512 + h]);
    float n = tanhf    (gi[base + 1024 + h] + r * gh[base + 1024 + h]);
    float d = (1.f - z) * n + z * deter_old[(size_t)b * NDETER + h];
    out[(size_t)b * OUTW + h] = d;
}

// ---------------------------------------------------------------------------
// Per-group-32 softmax -> unimix -> argmax one-hot (d_out cols [1536,2560))
// ---------------------------------------------------------------------------
__global__ void softmax_onehot_kernel(float* __restrict__ out)
{
    int gw   = (blockIdx.x * blockDim.x + threadIdx.x) >> 5;
    int lane = threadIdx.x & 31;
    int b    = gw >> 5;
    int grp  = gw & 31;
    float* row = out + (size_t)b * OUTW;
    float l = row[512 + grp * 32 + lane];
    float m = l;
#pragma unroll
    for (int o = 16; o > 0; o >>= 1) m = fmaxf(m, __shfl_xor_sync(0xffffffffu, m, o));
    float e = expf(l - m);
    float s = e;
#pragma unroll
    for (int o = 16; o > 0; o >>= 1) s += __shfl_xor_sync(0xffffffffu, s, o);
    float p = (1.f - UNIMIX) * (e / s) + UNIMIX / 32.f;
    float bp = p; int bi = lane;
#pragma unroll
    for (int o = 16; o > 0; o >>= 1) {
        float op = __shfl_xor_sync(0xffffffffu, bp, o);
        int   oi = __shfl_xor_sync(0xffffffffu, bi, o);
        if (op > bp || (op == bp && oi < bi)) { bp = op; bi = oi; }
    }
    row[1536 + grp * 32 + lane] = (lane == bi) ? 1.f : 0.f;
}

// ---------------------------------------------------------------------------
// Launch
// ---------------------------------------------------------------------------
extern "C" void kernel_launch(void* const* d_in, const int* in_sizes, int n_in,
                              void* d_out_, int out_size)
{
    const float* obs   = (const float*)d_in[0];
    const float* act   = (const float*)d_in[1];
    const float* stoch = (const float*)d_in[2];
    const float* deter = (const float*)d_in[3];
    const float* W_in  = (const float*)d_in[4];
    const float* gin   = (const float*)d_in[5];
    const float* bin   = (const float*)d_in[6];
    const float* W_ih  = (const float*)d_in[7];
    const float* W_hh  = (const float*)d_in[8];
    const float* b_ih  = (const float*)d_in[9];
    const float* b_hh  = (const float*)d_in[10];
    const float* W_obs = (const float*)d_in[11];
    const float* gobs  = (const float*)d_in[12];
    const float* bobs  = (const float*)d_in[13];
    const float* W_st  = (const float*)d_in[14];
    const float* b_st  = (const float*)d_in[15];
    float* out = (float*)d_out_;

    float *xbuf, *gi, *gh, *ybuf;
    cudaGetSymbolAddress((void**)&xbuf, g_xbuf);
    cudaGetSymbolAddress((void**)&gi,   g_gi);
    cudaGetSymbolAddress((void**)&gh,   g_gh);
    cudaGetSymbolAddress((void**)&ybuf, g_ybuf);

    cudaFuncSetAttribute(gemm_hmma, cudaFuncAttributeMaxDynamicSharedMemorySize, GEMM_SMEM);

    const int MT = B / 128;  // 128

    // 1) x_pre = [stoch | actions] @ W_in^T      (N=512, K=1084, K1=1024)
    gemm_hmma<<<dim3(HID / 128, MT), 256, GEMM_SMEM>>>(
        stoch, 1024, 1024, act, 60, W_in, nullptr, xbuf, HID, KIN);
    // 2) x = silu(LN(x_pre))
    ln_silu_kernel<<<B, 128>>>(xbuf, xbuf, gin, bin);
    // 3) gi = x @ W_ih^T + b_ih                  (N=1536, K=512)
    gemm_hmma<<<dim3(NGATE / 128, MT), 256, GEMM_SMEM>>>(
        xbuf, HID, HID, nullptr, 0, W_ih, b_ih, gi, NGATE, HID);
    // 4) gh = deter @ W_hh^T + b_hh
    gemm_hmma<<<dim3(NGATE / 128, MT), 256, GEMM_SMEM>>>(
        deter, NDETER, NDETER, nullptr, 0, W_hh, b_hh, gh, NGATE, NDETER);
    // 5) GRU -> deter_new in d_out[:, 0:512)
    gru_kernel<<<(B * NDETER) / 256, 256>>>(gi, gh, deter, out);
    // 6) y_pre = [deter_new | obs_enc] @ W_obs^T (N=512, K=5632, K1=512)
    gemm_hmma<<<dim3(HID / 128, MT), 256, GEMM_SMEM>>>(
        out, OUTW, NDETER, obs, 5120, W_obs, nullptr, ybuf, HID, KOBS);
    // 7) y = silu(LN(y_pre))
    ln_silu_kernel<<<B, 128>>>(ybuf, ybuf, gobs, bobs);
    // 8) logits = y @ W_stats^T + b_stats -> d_out[:, 512:1536)
    gemm_hmma<<<dim3(NSTATS / 128, MT), 256, GEMM_SMEM>>>(
        ybuf, HID, HID, nullptr, 0, W_st, b_st, out + 512, OUTW, HID);
    // 9) softmax/unimix/argmax one-hot -> d_out[:, 1536:2560)
    softmax_onehot_kernel<<<(B * 32 * 32) / 256, 256>>>(out);
}

// round 6
// speedup vs baseline: 2.0302x; 1.0332x over previous
#include <cuda_runtime.h>
#include <cuda_fp16.h>
#include <math.h>

// ---------------------------------------------------------------------------
// Problem constants
// ---------------------------------------------------------------------------
#define B       16384
#define HID     512
#define NDETER  512
#define NGATE   1536
#define KIN     1084
#define KOBS    5632
#define NSTATS  1024
#define OUTW    2560
#define LNEPS   1e-3f
#define UNIMIX  0.01f
#define LO_SCALE    2048.0f
#define LO_UNSCALE  (1.0f / 2048.0f)

// ---------------------------------------------------------------------------
// Scratch (device globals; no runtime allocation allowed)
// ---------------------------------------------------------------------------
__device__ float g_xbuf[(size_t)B * HID];
__device__ float g_gi  [(size_t)B * NGATE];
__device__ float g_gh  [(size_t)B * NGATE];
__device__ float g_ybuf[(size_t)B * HID];

// ---------------------------------------------------------------------------
// Helpers
// ---------------------------------------------------------------------------
__device__ __forceinline__ unsigned smem_u32(const void* p) {
    unsigned a;
    asm("{ .reg .u64 t; cvta.to.shared.u64 t, %1; cvt.u32.u64 %0, t; }"
        : "=r"(a) : "l"(p));
    return a;
}

#define MMA16816(acc, a, b0v, b1v)                                            \
    asm volatile(                                                             \
        "mma.sync.aligned.m16n8k16.row.col.f32.f16.f16.f32 "                  \
        "{%0,%1,%2,%3}, {%4,%5,%6,%7}, {%8,%9}, {%0,%1,%2,%3};"               \
        : "+f"((acc)[0]), "+f"((acc)[1]), "+f"((acc)[2]), "+f"((acc)[3])      \
        : "r"((a)[0]), "r"((a)[1]), "r"((a)[2]), "r"((a)[3]),                 \
          "r"(b0v), "r"(b1v))

#define LDMX4(r0, r1, r2, r3, addr)                                           \
    asm volatile("ldmatrix.sync.aligned.m8n8.x4.shared.b16 {%0,%1,%2,%3}, [%4];" \
        : "=r"(r0), "=r"(r1), "=r"(r2), "=r"(r3) : "r"(addr))

// ---------------------------------------------------------------------------
// fp16-split (Ootomo, scaled residual) HMMA GEMM:
//   C[M,N] = A[M,K] * W[N,K]^T (+ bias)
// x = hi + lo/2048 (fp16 hi, lo).  acc0 += hi*hi;  acc1 += hi*lo + lo*hi;
// C = acc0 + acc1/2048.  fp32 accumulators.
// CTA tile 128x128, K-chunk 32 fp32, 8 warps (2Mx4N), warp tile 64x32.
// smem stage: AH@0, AL@10240, BH@20480, BL@30720; stage stride 64KB so the
// per-chunk smem base is a 2-way select and every LDSM/STS address is
// baseReg + compile-time const (ptxas folds into the instruction immediate).
// MMA order: per m-tile 3 passes (acc0 aH*bH; acc1 aH*bL; acc1 aL*bH) ->
// RAW distance 4 on acc1 (was 1).  Per-acc accumulation order unchanged vs
// round 5 -> bit-identical results.
// ---------------------------------------------------------------------------
#define BKF     32
#define PITCH   80
#define AL_REL  10240u
#define BH_REL  20480u
#define STAGE_STRIDE 65536u
#define GEMM_SMEM (2 * 65536)

__global__ __launch_bounds__(256, 1)
void gemm_hmma(const float* __restrict__ A1, int lda1, int K1,
               const float* __restrict__ A2, int lda2,
               const float* __restrict__ W, const float* __restrict__ bias,
               float* __restrict__ C, int ldc, int K)
{
    extern __shared__ char smem[];
    const unsigned sb = smem_u32(smem);
    const int tid  = threadIdx.x;
    const int lane = tid & 31;
    const int wid  = tid >> 5;
    const int mW   = (wid >> 2) * 64;
    const int nW   = (wid & 3) * 32;
    const int mBase = blockIdx.y * 128;
    const int nBase = blockIdx.x * 128;

    float acc0[4][4][4];   // hi*hi
    float acc1[4][4][4];   // hi*lo + lo*hi (scaled by 2048)
#pragma unroll
    for (int i = 0; i < 4; i++)
#pragma unroll
        for (int j = 0; j < 4; j++)
#pragma unroll
            for (int c = 0; c < 4; c++) { acc0[i][j][c] = 0.f; acc1[i][j][c] = 0.f; }

    // ---- hoisted global pointers (one per q; advance by k0 per chunk) ----
    const int rowq = tid >> 3;            // 0..31
    const int c4b  = (tid & 7) * 4;       // k element offset of this thread
    const float* A2b = A2 ? A2 : A1;
    const int    ld2 = A2 ? lda2 : 0;
    const int    c4b2 = A2 ? c4b : 0;
    const float* pA1[4]; const float* pA2[4]; const float* pW[4];
#pragma unroll
    for (int q = 0; q < 4; ++q) {
        const int row = q * 32 + rowq;
        pA1[q] = A1  + (size_t)(mBase + row) * lda1 + c4b;
        pA2[q] = A2b + (size_t)(mBase + row) * ld2  + c4b2;
        pW[q]  = W   + (size_t)(nBase + row) * K    + c4b;
    }

    // ---- hoisted smem bases ----
    const unsigned stsBase0 = sb + (unsigned)(rowq * PITCH + (tid & 7) * 8);
    const unsigned stsBase1 = stsBase0 + STAGE_STRIDE;
    const unsigned aBase0 = sb + (unsigned)((mW + (lane & 15)) * PITCH + (lane >> 4) * 16);
    const unsigned aBase1 = aBase0 + STAGE_STRIDE;
    const unsigned bBase0 = sb + BH_REL
                          + (unsigned)((nW + (lane & 15)) * PITCH + (lane >> 4) * 16);
    const unsigned bBase1 = bBase0 + STAGE_STRIDE;

    const int nch = (K + BKF - 1) / BKF;

    float4 v[8];
    auto ldg_chunk = [&](int k0) {
        const bool seg1 = (k0 < K1);
        const int  kA   = seg1 ? k0 : k0 - K1;
        if (k0 + BKF <= K) {                 // full chunk: no predicates
#pragma unroll
            for (int q = 0; q < 4; ++q) {
                v[q]     = *(const float4*)((seg1 ? pA1[q] : pA2[q]) + kA);
                v[q + 4] = *(const float4*)(pW[q] + k0);
            }
        } else {
            const int rem = K - k0;
#pragma unroll
            for (int q = 0; q < 4; ++q) {
                float4 z = make_float4(0.f, 0.f, 0.f, 0.f);
                v[q]     = (c4b < rem) ? *(const float4*)((seg1 ? pA1[q] : pA2[q]) + kA) : z;
                v[q + 4] = (c4b < rem) ? *(const float4*)(pW[q] + k0) : z;
            }
        }
    };
    auto sts_chunk = [&](unsigned stsB) {
#pragma unroll
        for (int q = 0; q < 8; ++q) {
            const unsigned addr = stsB + (unsigned)((q & 3) * 32 * PITCH)
                                + (q < 4 ? 0u : BH_REL);
            const float4 x = v[q];
            __half2 h01 = __floats2half2_rn(x.x, x.y);
            __half2 h23 = __floats2half2_rn(x.z, x.w);
            float2 f01 = __half22float2(h01);
            float2 f23 = __half22float2(h23);
            __half2 l01 = __floats2half2_rn((x.x - f01.x) * LO_SCALE,
                                            (x.y - f01.y) * LO_SCALE);
            __half2 l23 = __floats2half2_rn((x.z - f23.x) * LO_SCALE,
                                            (x.w - f23.y) * LO_SCALE);
            unsigned uh0 = *(unsigned*)&h01, uh1 = *(unsigned*)&h23;
            unsigned ul0 = *(unsigned*)&l01, ul1 = *(unsigned*)&l23;
            asm volatile("st.shared.v2.b32 [%0], {%1,%2};"
                         :: "r"(addr), "r"(uh0), "r"(uh1) : "memory");
            asm volatile("st.shared.v2.b32 [%0], {%1,%2};"
                         :: "r"(addr + AL_REL), "r"(ul0), "r"(ul1) : "memory");
        }
    };

    ldg_chunk(0);
    sts_chunk(stsBase0);
    __syncthreads();

    for (int it = 0; it < nch; ++it) {
        const unsigned aB = (it & 1) ? aBase1 : aBase0;
        const unsigned bB = (it & 1) ? bBase1 : bBase0;
        if (it + 1 < nch) ldg_chunk((it + 1) * BKF);

#pragma unroll
        for (int kk = 0; kk < 2; ++kk) {
            // --- B fragments for this k16 (4 n-tiles, hi+lo) ---
            unsigned bH[4][2], bL[4][2];
#pragma unroll
            for (int np = 0; np < 2; ++np) {
                const unsigned bd = bB + (unsigned)(np * 16 * PITCH + kk * 32);
                unsigned r0, r1, r2, r3;
                LDMX4(r0, r1, r2, r3, bd);
                bH[2 * np][0] = r0; bH[2 * np][1] = r2;
                bH[2 * np + 1][0] = r1; bH[2 * np + 1][1] = r3;
                LDMX4(r0, r1, r2, r3, bd + AL_REL);
                bL[2 * np][0] = r0; bL[2 * np][1] = r2;
                bL[2 * np + 1][0] = r1; bL[2 * np + 1][1] = r3;
            }
            // --- A fragments double-buffered across mt ---
            unsigned aH[2][4], aL[2][4];
            {
                const unsigned ad = aB + (unsigned)(kk * 32);
                LDMX4(aH[0][0], aH[0][1], aH[0][2], aH[0][3], ad);
                LDMX4(aL[0][0], aL[0][1], aL[0][2], aL[0][3], ad + AL_REL);
            }
#pragma unroll
            for (int mt = 0; mt < 4; ++mt) {
                const int cur = mt & 1, nxt = cur ^ 1;
                if (mt < 3) {
                    const unsigned ad = aB + (unsigned)((mt + 1) * 16 * PITCH + kk * 32);
                    LDMX4(aH[nxt][0], aH[nxt][1], aH[nxt][2], aH[nxt][3], ad);
                    LDMX4(aL[nxt][0], aL[nxt][1], aL[nxt][2], aL[nxt][3], ad + AL_REL);
                }
#pragma unroll
                for (int nt = 0; nt < 4; ++nt)
                    MMA16816(acc0[mt][nt], aH[cur], bH[nt][0], bH[nt][1]);
#pragma unroll
                for (int nt = 0; nt < 4; ++nt)
                    MMA16816(acc1[mt][nt], aH[cur], bL[nt][0], bL[nt][1]);
#pragma unroll
                for (int nt = 0; nt < 4; ++nt)
                    MMA16816(acc1[mt][nt], aL[cur], bH[nt][0], bH[nt][1]);
            }
        }

        if (it + 1 < nch) sts_chunk((it & 1) ? stsBase0 : stsBase1);
        __syncthreads();
    }

    // ---- epilogue: C = acc0 + acc1/2048 (+bias) ----
    const int g = lane >> 2, t = lane & 3;
#pragma unroll
    for (int mt = 0; mt < 4; ++mt) {
#pragma unroll
        for (int nt = 0; nt < 4; ++nt) {
            const int row = mBase + mW + mt * 16 + g;
            const int col = nBase + nW + nt * 8 + t * 2;
            float bx = 0.f, by = 0.f;
            if (bias) { bx = bias[col]; by = bias[col + 1]; }
            float2 o0, o1;
            o0.x = fmaf(acc1[mt][nt][0], LO_UNSCALE, acc0[mt][nt][0]) + bx;
            o0.y = fmaf(acc1[mt][nt][1], LO_UNSCALE, acc0[mt][nt][1]) + by;
            o1.x = fmaf(acc1[mt][nt][2], LO_UNSCALE, acc0[mt][nt][2]) + bx;
            o1.y = fmaf(acc1[mt][nt][3], LO_UNSCALE, acc0[mt][nt][3]) + by;
            *(float2*)(C + (size_t)row * ldc + col)       = o0;
            *(float2*)(C + (size_t)(row + 8) * ldc + col) = o1;
        }
    }
}

// ---------------------------------------------------------------------------
// LayerNorm(eps=1e-3) + SiLU (rows of 512; 128 threads/row)
// ---------------------------------------------------------------------------
__device__ __forceinline__ float block_reduce_128(float v, float* sm)
{
#pragma unroll
    for (int o = 16; o > 0; o >>= 1) v += __shfl_xor_sync(0xffffffffu, v, o);
    int w = threadIdx.x >> 5;
    if ((threadIdx.x & 31) == 0) sm[w] = v;
    __syncthreads();
    float r = sm[0] + sm[1] + sm[2] + sm[3];
    __syncthreads();
    return r;
}

__global__ void ln_silu_kernel(const float* __restrict__ in, float* __restrict__ out,
                               const float* __restrict__ g, const float* __restrict__ bb)
{
    __shared__ float sm[4];
    const int row = blockIdx.x;
    const float4 v = ((const float4*)(in + (size_t)row * HID))[threadIdx.x];
    float s = v.x + v.y + v.z + v.w;
    float mean = block_reduce_128(s, sm) * (1.f / HID);
    float dx = v.x - mean, dy = v.y - mean, dz = v.z - mean, dw = v.w - mean;
    float q = dx * dx + dy * dy + dz * dz + dw * dw;
    float var = block_reduce_128(q, sm) * (1.f / HID);
    float rs = rsqrtf(var + LNEPS);
    float4 gg = ((const float4*)g)[threadIdx.x];
    float4 bv = ((const float4*)bb)[threadIdx.x];
    float t0 = dx * rs * gg.x + bv.x;
    float t1 = dy * rs * gg.y + bv.y;
    float t2 = dz * rs * gg.z + bv.z;
    float t3 = dw * rs * gg.w + bv.w;
    float4 o;
    o.x = t0 / (1.f + expf(-t0));
    o.y = t1 / (1.f + expf(-t1));
    o.z = t2 / (1.f + expf(-t2));
    o.w = t3 / (1.f + expf(-t3));
    ((float4*)(out + (size_t)row * HID))[threadIdx.x] = o;
}

// ---------------------------------------------------------------------------
// GRU gates (torch order r,z,n) -> deter into d_out cols [0,512)
// ---------------------------------------------------------------------------
__device__ __forceinline__ float sigmoidf_(float x) { return 1.f / (1.f + expf(-x)); }

__global__ void gru_kernel(const float* __restrict__ gi, const float* __restrict__ gh,
                           const float* __restrict__ deter_old, float* __restrict__ out)
{
    int idx = blockIdx.x * blockDim.x + threadIdx.x;
    int b = idx >> 9;
    int h = idx & 511;
    size_t base = (size_t)b * NGATE;
    float r = sigmoidf_(gi[base + h]        + gh[base + h]);
    float z = sigmoidf_(gi[base + 512 + h]  + gh[base + 512 + h]);
    float n = tanhf    (gi[base + 1024 + h] + r * gh[base + 1024 + h]);
    float d = (1.f - z) * n + z * deter_old[(size_t)b * NDETER + h];
    out[(size_t)b * OUTW + h] = d;
}

// ---------------------------------------------------------------------------
// Per-group-32 softmax -> unimix -> argmax one-hot (d_out cols [1536,2560))
// ---------------------------------------------------------------------------
__global__ void softmax_onehot_kernel(float* __restrict__ out)
{
    int gw   = (blockIdx.x * blockDim.x + threadIdx.x) >> 5;
    int lane = threadIdx.x & 31;
    int b    = gw >> 5;
    int grp  = gw & 31;
    float* row = out + (size_t)b * OUTW;
    float l = row[512 + grp * 32 + lane];
    float m = l;
#pragma unroll
    for (int o = 16; o > 0; o >>= 1) m = fmaxf(m, __shfl_xor_sync(0xffffffffu, m, o));
    float e = expf(l - m);
    float s = e;
#pragma unroll
    for (int o = 16; o > 0; o >>= 1) s += __shfl_xor_sync(0xffffffffu, s, o);
    float p = (1.f - UNIMIX) * (e / s) + UNIMIX / 32.f;
    float bp = p; int bi = lane;
#pragma unroll
    for (int o = 16; o > 0; o >>= 1) {
        float op = __shfl_xor_sync(0xffffffffu, bp, o);
        int   oi = __shfl_xor_sync(0xffffffffu, bi, o);
        if (op > bp || (op == bp && oi < bi)) { bp = op; bi = oi; }
    }
    row[1536 + grp * 32 + lane] = (lane == bi) ? 1.f : 0.f;
}

// ---------------------------------------------------------------------------
// Launch
// ---------------------------------------------------------------------------
extern "C" void kernel_launch(void* const* d_in, const int* in_sizes, int n_in,
                              void* d_out_, int out_size)
{
    const float* obs   = (const float*)d_in[0];
    const float* act   = (const float*)d_in[1];
    const float* stoch = (const float*)d_in[2];
    const float* deter = (const float*)d_in[3];
    const float* W_in  = (const float*)d_in[4];
    const float* gin   = (const float*)d_in[5];
    const float* bin   = (const float*)d_in[6];
    const float* W_ih  = (const float*)d_in[7];
    const float* W_hh  = (const float*)d_in[8];
    const float* b_ih  = (const float*)d_in[9];
    const float* b_hh  = (const float*)d_in[10];
    const float* W_obs = (const float*)d_in[11];
    const float* gobs  = (const float*)d_in[12];
    const float* bobs  = (const float*)d_in[13];
    const float* W_st  = (const float*)d_in[14];
    const float* b_st  = (const float*)d_in[15];
    float* out = (float*)d_out_;

    float *xbuf, *gi, *gh, *ybuf;
    cudaGetSymbolAddress((void**)&xbuf, g_xbuf);
    cudaGetSymbolAddress((void**)&gi,   g_gi);
    cudaGetSymbolAddress((void**)&gh,   g_gh);
    cudaGetSymbolAddress((void**)&ybuf, g_ybuf);

    cudaFuncSetAttribute(gemm_hmma, cudaFuncAttributeMaxDynamicSharedMemorySize, GEMM_SMEM);

    const int MT = B / 128;  // 128

    // 1) x_pre = [stoch | actions] @ W_in^T      (N=512, K=1084, K1=1024)
    gemm_hmma<<<dim3(HID / 128, MT), 256, GEMM_SMEM>>>(
        stoch, 1024, 1024, act, 60, W_in, nullptr, xbuf, HID, KIN);
    // 2) x = silu(LN(x_pre))
    ln_silu_kernel<<<B, 128>>>(xbuf, xbuf, gin, bin);
    // 3) gi = x @ W_ih^T + b_ih                  (N=1536, K=512)
    gemm_hmma<<<dim3(NGATE / 128, MT), 256, GEMM_SMEM>>>(
        xbuf, HID, HID, nullptr, 0, W_ih, b_ih, gi, NGATE, HID);
    // 4) gh = deter @ W_hh^T + b_hh
    gemm_hmma<<<dim3(NGATE / 128, MT), 256, GEMM_SMEM>>>(
        deter, NDETER, NDETER, nullptr, 0, W_hh, b_hh, gh, NGATE, NDETER);
    // 5) GRU -> deter_new in d_out[:, 0:512)
    gru_kernel<<<(B * NDETER) / 256, 256>>>(gi, gh, deter, out);
    // 6) y_pre = [deter_new | obs_enc] @ W_obs^T (N=512, K=5632, K1=512)
    gemm_hmma<<<dim3(HID / 128, MT), 256, GEMM_SMEM>>>(
        out, OUTW, NDETER, obs, 5120, W_obs, nullptr, ybuf, HID, KOBS);
    // 7) y = silu(LN(y_pre))
    ln_silu_kernel<<<B, 128>>>(ybuf, ybuf, gobs, bobs);
    // 8) logits = y @ W_stats^T + b_stats -> d_out[:, 512:1536)
    gemm_hmma<<<dim3(NSTATS / 128, MT), 256, GEMM_SMEM>>>(
        ybuf, HID, HID, nullptr, 0, W_st, b_st, out + 512, OUTW, HID);
    // 9) softmax/unimix/argmax one-hot -> d_out[:, 1536:2560)
    softmax_onehot_kernel<<<(B * 32 * 32) / 256, 256>>>(out);
}